// round 11
// baseline (speedup 1.0000x reference)
#include <cuda_runtime.h>
#include <cstdint>

#define B  4
#define T  1024
#define DM 512
#define NH 8
#define DK 64

// ---------------- scratch (device globals; no allocs allowed) ----------------
__device__ float g_Q[B * NH * T * DK];
__device__ float g_K[B * NH * T * DK];
__device__ float g_V[B * NH * T * DK];
__device__ float g_M[(size_t)B * NH * T * T];
__device__ float g_Mt[(size_t)B * NH * T * T];
__device__ float g_Ctx[B * T * DM];

// =============================================================================
// Tensor-core building blocks: split-TF32 (3xTF32) m16n8k8 MMA
// =============================================================================
__device__ __forceinline__ void split_tf32(float x, uint32_t& hi, uint32_t& lo) {
    asm("cvt.rna.tf32.f32 %0, %1;" : "=r"(hi) : "f"(x));
    float l = x - __uint_as_float(hi);
    asm("cvt.rna.tf32.f32 %0, %1;" : "=r"(lo) : "f"(l));
}

__device__ __forceinline__ void mma_tf32(float* c, const uint32_t* a, const uint32_t* b) {
    asm("mma.sync.aligned.m16n8k8.row.col.f32.tf32.tf32.f32 "
        "{%0,%1,%2,%3}, {%4,%5,%6,%7}, {%8,%9}, {%0,%1,%2,%3};"
        : "+f"(c[0]), "+f"(c[1]), "+f"(c[2]), "+f"(c[3])
        : "r"(a[0]), "r"(a[1]), "r"(a[2]), "r"(a[3]), "r"(b[0]), "r"(b[1]));
}

#define LDSS 36   // smem row stride (floats) for 32-wide k tiles (+4 pad)

// Load a ROWS x 32 tile (row-major, leading dim ld) into smem [row][k] w/ stride LDSS
template<int ROWS>
__device__ __forceinline__ void load_tile(float* S, const float* src, int ld) {
    int t = threadIdx.x;
    int r = t >> 3, c4 = (t & 7) * 4;
    #pragma unroll
    for (int i = 0; i < ROWS / 32; i++) {
        float4 v = *(const float4*)&src[(size_t)(r + i * 32) * ld + c4];
        *(float4*)&S[(r + i * 32) * LDSS + c4] = v;
    }
}

// One 32-deep k-chunk of 3xTF32 MMAs.
// A smem: [m][k] stride LDSS. B smem: if BK==0: [n][k] stride LDSS; if BK==1: [k][n] stride 68.
template<int MT, int NT, int BK>
__device__ __forceinline__ void mma_chunk(const float* As, const float* Bs,
                                          int mbase, int nbase, float acc[][4]) {
    int lane = threadIdx.x & 31;
    int g = lane >> 2, t4 = lane & 3;
    #pragma unroll
    for (int k8 = 0; k8 < 4; k8++) {
        const int k0 = k8 * 8;
        uint32_t bhi[NT][2], blo[NT][2];
        #pragma unroll
        for (int nt = 0; nt < NT; nt++) {
            float b0, b1;
            if (BK == 0) {
                const float* bp = Bs + (nbase + nt * 8 + g) * LDSS + k0 + t4;
                b0 = bp[0]; b1 = bp[4];
            } else {
                const float* bp = Bs + (k0 + t4) * 68 + nbase + nt * 8 + g;
                b0 = bp[0]; b1 = bp[4 * 68];
            }
            split_tf32(b0, bhi[nt][0], blo[nt][0]);
            split_tf32(b1, bhi[nt][1], blo[nt][1]);
        }
        #pragma unroll
        for (int mt = 0; mt < MT; mt++) {
            const float* ap = As + (mbase + mt * 16 + g) * LDSS + k0 + t4;
            uint32_t ahi[4], alo[4];
            split_tf32(ap[0],             ahi[0], alo[0]);
            split_tf32(ap[8 * LDSS],      ahi[1], alo[1]);
            split_tf32(ap[4],             ahi[2], alo[2]);
            split_tf32(ap[8 * LDSS + 4],  ahi[3], alo[3]);
            #pragma unroll
            for (int nt = 0; nt < NT; nt++) {
                float* c = acc[mt * NT + nt];
                mma_tf32(c, ahi, bhi[nt]);
                mma_tf32(c, ahi, blo[nt]);
                mma_tf32(c, alo, bhi[nt]);
            }
        }
    }
}

// =============================================================================
// QKV projections (tensor): C = X @ W^T, scatter to (B,H,T,DK). 128x128 tiles.
// =============================================================================
__global__ void __launch_bounds__(256) tgemm_qkv(const float* __restrict__ q,
                                                 const float* __restrict__ k,
                                                 const float* __restrict__ v,
                                                 const float* __restrict__ w_q,
                                                 const float* __restrict__ w_k,
                                                 const float* __restrict__ w_v) {
    __shared__ float As[128 * LDSS];
    __shared__ float Bs[128 * LDSS];

    int z = blockIdx.z;
    const float* A = (z == 0) ? q : (z == 1) ? k : v;
    const float* W = (z == 0) ? w_q : (z == 1) ? w_k : w_v;
    float* C = (z == 0) ? g_Q : (z == 1) ? g_K : g_V;

    int m0 = blockIdx.y * 128, n0 = blockIdx.x * 128;
    int wid = threadIdx.x >> 5;
    int mbase = (wid >> 2) * 64, nbase = (wid & 3) * 32;

    float acc[16][4];
    #pragma unroll
    for (int i = 0; i < 16; i++)
        #pragma unroll
        for (int j = 0; j < 4; j++) acc[i][j] = 0.f;

    for (int k0 = 0; k0 < 512; k0 += 32) {
        load_tile<128>(As, A + (size_t)m0 * 512 + k0, 512);
        load_tile<128>(Bs, W + (size_t)n0 * 512 + k0, 512);
        __syncthreads();
        mma_chunk<4, 4, 0>(As, Bs, mbase, nbase, acc);
        __syncthreads();
    }

    int lane = threadIdx.x & 31, g = lane >> 2, t4 = lane & 3;
    #pragma unroll
    for (int mt = 0; mt < 4; mt++) {
        #pragma unroll
        for (int nt = 0; nt < 4; nt++) {
            int col = n0 + nbase + nt * 8 + t4 * 2;
            int h = col >> 6, d = col & 63;
            int r0 = m0 + mbase + mt * 16 + g;
            int r1 = r0 + 8;
            float* c = acc[mt * 4 + nt];
            *(float2*)&C[(size_t)(((r0 >> 10) * NH + h) * T + (r0 & 1023)) * DK + d] =
                make_float2(c[0], c[1]);
            *(float2*)&C[(size_t)(((r1 >> 10) * NH + h) * T + (r1 & 1023)) * DK + d] =
                make_float2(c[2], c[3]);
        }
    }
}

// =============================================================================
// Output projection (tensor): out = g_Ctx @ w_o^T
// =============================================================================
__global__ void __launch_bounds__(256) tgemm_wo(const float* __restrict__ W,
                                                float* __restrict__ out) {
    __shared__ float As[128 * LDSS];
    __shared__ float Bs[128 * LDSS];

    int m0 = blockIdx.y * 128, n0 = blockIdx.x * 128;
    int wid = threadIdx.x >> 5;
    int mbase = (wid >> 2) * 64, nbase = (wid & 3) * 32;

    float acc[16][4];
    #pragma unroll
    for (int i = 0; i < 16; i++)
        #pragma unroll
        for (int j = 0; j < 4; j++) acc[i][j] = 0.f;

    for (int k0 = 0; k0 < 512; k0 += 32) {
        load_tile<128>(As, g_Ctx + (size_t)m0 * 512 + k0, 512);
        load_tile<128>(Bs, W + (size_t)n0 * 512 + k0, 512);
        __syncthreads();
        mma_chunk<4, 4, 0>(As, Bs, mbase, nbase, acc);
        __syncthreads();
    }

    int lane = threadIdx.x & 31, g = lane >> 2, t4 = lane & 3;
    #pragma unroll
    for (int mt = 0; mt < 4; mt++) {
        #pragma unroll
        for (int nt = 0; nt < 4; nt++) {
            int col = n0 + nbase + nt * 8 + t4 * 2;
            int r0 = m0 + mbase + mt * 16 + g;
            int r1 = r0 + 8;
            float* c = acc[mt * 4 + nt];
            *(float2*)&out[(size_t)r0 * 512 + col] = make_float2(c[0], c[1]);
            *(float2*)&out[(size_t)r1 * 512 + col] = make_float2(c[2], c[3]);
        }
    }
}

// =============================================================================
// M = Q K^T per (b,h) (tensor). 128x128 tiles, K=64.
// =============================================================================
__global__ void __launch_bounds__(256) tqk_kernel() {
    __shared__ float As[128 * LDSS];
    __shared__ float Bs[128 * LDSS];

    int bh = blockIdx.z;
    const float* Qb = g_Q + (size_t)bh * T * DK;
    const float* Kb = g_K + (size_t)bh * T * DK;
    int m0 = blockIdx.y * 128, n0 = blockIdx.x * 128;
    int wid = threadIdx.x >> 5;
    int mbase = (wid >> 2) * 64, nbase = (wid & 3) * 32;

    float acc[16][4];
    #pragma unroll
    for (int i = 0; i < 16; i++)
        #pragma unroll
        for (int j = 0; j < 4; j++) acc[i][j] = 0.f;

    for (int k0 = 0; k0 < 64; k0 += 32) {
        load_tile<128>(As, Qb + (size_t)m0 * DK + k0, DK);
        load_tile<128>(Bs, Kb + (size_t)n0 * DK + k0, DK);
        __syncthreads();
        mma_chunk<4, 4, 0>(As, Bs, mbase, nbase, acc);
        __syncthreads();
    }

    float* Mb = g_M + (size_t)bh * T * T;
    int lane = threadIdx.x & 31, g = lane >> 2, t4 = lane & 3;
    #pragma unroll
    for (int mt = 0; mt < 4; mt++) {
        #pragma unroll
        for (int nt = 0; nt < 4; nt++) {
            int col = n0 + nbase + nt * 8 + t4 * 2;
            int r0 = m0 + mbase + mt * 16 + g;
            int r1 = r0 + 8;
            float* c = acc[mt * 4 + nt];
            *(float2*)&Mb[(size_t)r0 * T + col] = make_float2(c[0], c[1]);
            *(float2*)&Mb[(size_t)r1 * T + col] = make_float2(c[2], c[3]);
        }
    }
}

// =============================================================================
// Ctx = A @ V per (b,h) (tensor). 128x64 tiles, K=1024. V kept k-major in smem.
// =============================================================================
__global__ void __launch_bounds__(256) tav_kernel(const float* __restrict__ A) {
    __shared__ float As[128 * LDSS];
    __shared__ float Vs[32 * 68];

    int bh = blockIdx.y;
    int b = bh >> 3, h = bh & 7;
    const float* Ab = A + (size_t)bh * T * T;
    const float* Vb = g_V + (size_t)bh * T * DK;
    int m0 = blockIdx.x * 128;
    int wid = threadIdx.x >> 5;
    int mbase = (wid >> 1) * 32, nbase = (wid & 1) * 32;

    float acc[8][4];
    #pragma unroll
    for (int i = 0; i < 8; i++)
        #pragma unroll
        for (int j = 0; j < 4; j++) acc[i][j] = 0.f;

    int t = threadIdx.x;
    int vr = t >> 4, vc4 = (t & 15) * 4;

    for (int k0 = 0; k0 < T; k0 += 32) {
        load_tile<128>(As, Ab + (size_t)m0 * T + k0, T);
        #pragma unroll
        for (int i = 0; i < 2; i++) {
            float4 vv = *(const float4*)&Vb[(size_t)(k0 + vr + i * 16) * DK + vc4];
            *(float4*)&Vs[(vr + i * 16) * 68 + vc4] = vv;
        }
        __syncthreads();
        mma_chunk<2, 4, 1>(As, Vs, mbase, nbase, acc);
        __syncthreads();
    }

    int lane = threadIdx.x & 31, g = lane >> 2, t4 = lane & 3;
    #pragma unroll
    for (int mt = 0; mt < 2; mt++) {
        #pragma unroll
        for (int nt = 0; nt < 4; nt++) {
            int d = nbase + nt * 8 + t4 * 2;
            int r0 = m0 + mbase + mt * 16 + g;
            int r1 = r0 + 8;
            float* c = acc[mt * 4 + nt];
            *(float2*)&g_Ctx[(size_t)(b * T + r0) * DM + h * DK + d] = make_float2(c[0], c[1]);
            *(float2*)&g_Ctx[(size_t)(b * T + r1) * DM + h * DK + d] = make_float2(c[2], c[3]);
        }
    }
}

// =============================================================================
// Implicit-GEMM conv3x3 (tensor core). CTA: 64x8 output pixels, 256 threads.
// smem tile: [yy 0..9][xx 0..65][c 0..7] with channel slot padded to 12 floats
// (x-stride 12 => conflict-free A-fragment LDS: g*12+t4 covers all 32 banks).
// Warp w owns output row y0+w; 4 m-tiles of 16 pixels; N=8 output channels.
// =============================================================================
#define CXS 12          // channel-slot stride (floats)
#define CRS (66 * CXS)  // row stride = 792 floats

// Load one 8-channel halo tile (warp w loads channel w).
__device__ __forceinline__ void conv_load_tile(float* __restrict__ s,
                                               const float* __restrict__ src_b,
                                               int y0, int x0) {
    int w = threadIdx.x >> 5, lane = threadIdx.x & 31;
    const float* plane = src_b + (size_t)w * T * T;
    #pragma unroll
    for (int yy = 0; yy < 10; yy++) {
        int y = y0 - 1 + yy;
        bool yok = ((unsigned)y < T);
        int xA = x0 - 1 + lane;
        float v0 = 0.f, v1 = 0.f;
        if (yok) {
            if (xA >= 0) v0 = plane[(size_t)y * T + xA];
            v1 = plane[(size_t)y * T + xA + 32];          // always in-bounds (<= 1022)
        }
        s[yy * CRS + lane * CXS + w] = v0;
        s[yy * CRS + (lane + 32) * CXS + w] = v1;
        if (lane < 2) {
            int xC = x0 + 63 + lane;
            float v2 = 0.f;
            if (yok && xC < T) v2 = plane[(size_t)y * T + xC];
            s[yy * CRS + (64 + lane) * CXS + w] = v2;
        }
    }
}

// Split conv weights for one 8-channel pass into registers.
// W layout: [oc][cin][3][3]; this thread supplies B[k=t4][n=g] and B[k=t4+4][n=g].
__device__ __forceinline__ void conv_load_wregs(const float* __restrict__ W, int cin, int c0,
                                                int g, int t4,
                                                uint32_t bh0[9], uint32_t bl0[9],
                                                uint32_t bh1[9], uint32_t bl1[9]) {
    #pragma unroll
    for (int tap = 0; tap < 9; tap++) {
        float w0 = W[(g * cin + c0 + t4) * 9 + tap];
        float w1 = W[(g * cin + c0 + t4 + 4) * 9 + tap];
        split_tf32(w0, bh0[tap], bl0[tap]);
        split_tf32(w1, bh1[tap], bl1[tap]);
    }
}

// One 8-channel pass: accumulate 9 taps x 3xTF32 MMA into acc[4 m-tiles][4].
__device__ __forceinline__ void conv_mma_pass(const float* __restrict__ s, int g,
                                              const uint32_t bh0[9], const uint32_t bl0[9],
                                              const uint32_t bh1[9], const uint32_t bl1[9],
                                              float acc[4][4]) {
    #pragma unroll
    for (int xt = 0; xt < 4; xt++) {
        const float* mp = s + (xt * 16 + g) * CXS;
        #pragma unroll
        for (int dy = 0; dy < 3; dy++) {
            #pragma unroll
            for (int dx = 0; dx < 3; dx++) {
                int tap = dy * 3 + dx;
                const float* ap = mp + dy * CRS + dx * CXS;
                uint32_t ahi[4], alo[4];
                split_tf32(ap[0],            ahi[0], alo[0]);
                split_tf32(ap[8 * CXS],      ahi[1], alo[1]);
                split_tf32(ap[4],            ahi[2], alo[2]);
                split_tf32(ap[8 * CXS + 4],  ahi[3], alo[3]);
                uint32_t bh[2] = {bh0[tap], bh1[tap]};
                uint32_t bl[2] = {bl0[tap], bl1[tap]};
                mma_tf32(acc[xt], ahi, bh);
                mma_tf32(acc[xt], ahi, bl);
                mma_tf32(acc[xt], alo, bh);
            }
        }
    }
}

// Mt = conv3x3(prev, tw) + tb  (8 -> 8 ch), tensor-core implicit GEMM.
__global__ void __launch_bounds__(256) conv_mt_mma(const float* __restrict__ prev,
                                                   const float* __restrict__ tw,
                                                   const float* __restrict__ tb) {
    __shared__ float s[10 * CRS];
    int b = blockIdx.z, x0 = blockIdx.x * 64, y0 = blockIdx.y * 8;
    int w = threadIdx.x >> 5, lane = threadIdx.x & 31;
    int g = lane >> 2, t4 = lane & 3;

    conv_load_tile(s, prev + (size_t)b * 8 * T * T, y0, x0);

    uint32_t bh0[9], bl0[9], bh1[9], bl1[9];
    conv_load_wregs(tw, 8, 0, g, t4, bh0, bl0, bh1, bl1);
    __syncthreads();

    float acc[4][4];
    #pragma unroll
    for (int i = 0; i < 4; i++)
        #pragma unroll
        for (int j = 0; j < 4; j++) acc[i][j] = 0.f;

    conv_mma_pass(s + w * CRS + t4, g, bh0, bl0, bh1, bl1, acc);

    float bias0 = tb[2 * t4], bias1 = tb[2 * t4 + 1];
    int y = y0 + w;
    float* p0 = &g_Mt[((size_t)(b * 8 + 2 * t4) * T + y) * T];
    float* p1 = &g_Mt[((size_t)(b * 8 + 2 * t4 + 1) * T + y) * T];
    #pragma unroll
    for (int xt = 0; xt < 4; xt++) {
        int px = x0 + xt * 16 + g;
        p0[px]     = acc[xt][0] + bias0;
        p1[px]     = acc[xt][1] + bias1;
        p0[px + 8] = acc[xt][2] + bias0;
        p1[px + 8] = acc[xt][3] + bias1;
    }
}

// Apre = (conv3x3(concat(M, Mt), aw) + ab) / 8, masked -> A region of d_out.
__global__ void __launch_bounds__(256) conv_ma_mma(const float* __restrict__ aw,
                                                   const float* __restrict__ ab,
                                                   const int* __restrict__ mask,
                                                   float* __restrict__ Apre) {
    __shared__ float s[10 * CRS];
    int b = blockIdx.z, x0 = blockIdx.x * 64, y0 = blockIdx.y * 8;
    int w = threadIdx.x >> 5, lane = threadIdx.x & 31;
    int g = lane >> 2, t4 = lane & 3;

    float acc[4][4];
    #pragma unroll
    for (int i = 0; i < 4; i++)
        #pragma unroll
        for (int j = 0; j < 4; j++) acc[i][j] = 0.f;

    #pragma unroll
    for (int pass = 0; pass < 2; pass++) {
        const float* src = pass ? g_Mt : g_M;
        if (pass) __syncthreads();   // previous pass compute done before overwrite
        conv_load_tile(s, src + (size_t)b * 8 * T * T, y0, x0);

        uint32_t bh0[9], bl0[9], bh1[9], bl1[9];
        conv_load_wregs(aw, 16, pass * 8, g, t4, bh0, bl0, bh1, bl1);
        __syncthreads();

        conv_mma_pass(s + w * CRS + t4, g, bh0, bl0, bh1, bl1, acc);
    }

    float bias0 = ab[2 * t4], bias1 = ab[2 * t4 + 1];
    int y = y0 + w;
    float* p0 = &Apre[((size_t)(b * 8 + 2 * t4) * T + y) * T];
    float* p1 = &Apre[((size_t)(b * 8 + 2 * t4 + 1) * T + y) * T];
    #pragma unroll
    for (int xt = 0; xt < 4; xt++) {
        int px = x0 + xt * 16 + g;
        int mk0 = mask[b * T + px];
        int mk1 = mask[b * T + px + 8];
        float r00 = (acc[xt][0] + bias0) * 0.125f;
        float r01 = (acc[xt][1] + bias1) * 0.125f;
        float r10 = (acc[xt][2] + bias0) * 0.125f;
        float r11 = (acc[xt][3] + bias1) * 0.125f;
        if (mk0 == 0) { r00 = -1e9f; r01 = -1e9f; }
        if (mk1 == 0) { r10 = -1e9f; r11 = -1e9f; }
        p0[px]     = r00;
        p1[px]     = r01;
        p0[px + 8] = r10;
        p1[px + 8] = r11;
    }
}

// ---------------- warp-per-row softmax (rows of 1024), in place ---------------
__global__ void __launch_bounds__(256) softmax_kernel(float* __restrict__ A) {
    int row = blockIdx.x * 8 + (threadIdx.x >> 5);
    int lane = threadIdx.x & 31;
    float* p = A + (size_t)row * 1024;

    float4 v[8];
    #pragma unroll
    for (int j = 0; j < 8; j++) v[j] = *(float4*)&p[(j * 32 + lane) * 4];

    float mx = -3.4e38f;
    #pragma unroll
    for (int j = 0; j < 8; j++)
        mx = fmaxf(mx, fmaxf(fmaxf(v[j].x, v[j].y), fmaxf(v[j].z, v[j].w)));
    #pragma unroll
    for (int o = 16; o > 0; o >>= 1) mx = fmaxf(mx, __shfl_xor_sync(~0u, mx, o));

    float s = 0.f;
    #pragma unroll
    for (int j = 0; j < 8; j++) {
        v[j].x = __expf(v[j].x - mx); v[j].y = __expf(v[j].y - mx);
        v[j].z = __expf(v[j].z - mx); v[j].w = __expf(v[j].w - mx);
        s += v[j].x + v[j].y + v[j].z + v[j].w;
    }
    #pragma unroll
    for (int o = 16; o > 0; o >>= 1) s += __shfl_xor_sync(~0u, s, o);
    float inv = 1.f / s;

    #pragma unroll
    for (int j = 0; j < 8; j++) {
        v[j].x *= inv; v[j].y *= inv; v[j].z *= inv; v[j].w *= inv;
        *(float4*)&p[(j * 32 + lane) * 4] = v[j];
    }
}

// ---------------- launcher ---------------------------------------------------
extern "C" void kernel_launch(void* const* d_in, const int* in_sizes, int n_in,
                              void* d_out, int out_size) {
    const float* q    = (const float*)d_in[0];
    const float* k    = (const float*)d_in[1];
    const float* v    = (const float*)d_in[2];
    const int*   mask = (const int*)  d_in[3];
    const float* prev = (const float*)d_in[4];
    const float* w_q  = (const float*)d_in[5];
    const float* w_k  = (const float*)d_in[6];
    const float* w_v  = (const float*)d_in[7];
    const float* w_o  = (const float*)d_in[8];
    const float* tw   = (const float*)d_in[9];
    const float* tb   = (const float*)d_in[10];
    const float* aw   = (const float*)d_in[11];
    const float* ab   = (const float*)d_in[12];

    float* out  = (float*)d_out;
    float* Aout = out + (size_t)B * T * DM;

    // One-time host-side resources (created on the correctness call, reused
    // under graph capture; only event record/wait are issued per call).
    static cudaStream_t s_side = ([]() {
        cudaStream_t s; cudaStreamCreateWithFlags(&s, cudaStreamNonBlocking); return s;
    })();
    static cudaEvent_t ev_fork = ([]() {
        cudaEvent_t e; cudaEventCreateWithFlags(&e, cudaEventDisableTiming); return e;
    })();
    static cudaEvent_t ev_join = ([]() {
        cudaEvent_t e; cudaEventCreateWithFlags(&e, cudaEventDisableTiming); return e;
    })();

    // ---- fork: conv_mt (depends only on prev) runs on side stream ----------
    cudaEventRecord(ev_fork, 0);
    cudaStreamWaitEvent(s_side, ev_fork, 0);
    conv_mt_mma<<<dim3(T / 64, T / 8, B), 256, 0, s_side>>>(prev, tw, tb);
    cudaEventRecord(ev_join, s_side);

    // ---- main chain on default stream (overlaps with conv_mt) --------------
    tgemm_qkv<<<dim3(DM / 128, (B * T) / 128, 3), 256>>>(q, k, v, w_q, w_k, w_v);
    tqk_kernel<<<dim3(T / 128, T / 128, B * NH), 256>>>();

    // ---- join: conv_ma needs both g_M and g_Mt -----------------------------
    cudaStreamWaitEvent(0, ev_join, 0);
    conv_ma_mma<<<dim3(T / 64, T / 8, B), 256>>>(aw, ab, mask, Aout);

    softmax_kernel<<<(B * NH * T) / 8, 256>>>(Aout);
    tav_kernel<<<dim3(T / 128, B * NH), 256>>>(Aout);
    tgemm_wo<<<dim3(DM / 128, (B * T) / 128), 256>>>(w_o, out);
}

// round 12
// speedup vs baseline: 1.2272x; 1.2272x over previous
#include <cuda_runtime.h>
#include <cstdint>

#define B  4
#define T  1024
#define DM 512
#define NH 8
#define DK 64

// ---------------- scratch (device globals; no allocs allowed) ----------------
__device__ float g_Q[B * NH * T * DK];
__device__ float g_K[B * NH * T * DK];
__device__ float g_V[B * NH * T * DK];
__device__ float g_M[(size_t)B * NH * T * T];
__device__ float g_Mt[(size_t)B * NH * T * T];
__device__ float g_Ctx[B * T * DM];

// packed f32x2 FMA (PTX-only) — used by the scalar conv_mt
union F2U { float2 f; unsigned long long u; };
__device__ __forceinline__ void ffma2(float2& c, float2 a, float2 b) {
    F2U A, Bv, C;
    A.f = a; Bv.f = b; C.f = c;
    asm("fma.rn.f32x2 %0, %1, %2, %0;" : "+l"(C.u) : "l"(A.u), "l"(Bv.u));
    c = C.f;
}

// =============================================================================
// Tensor-core building blocks: split-TF32 (3xTF32) m16n8k8 MMA
// =============================================================================
__device__ __forceinline__ void split_tf32(float x, uint32_t& hi, uint32_t& lo) {
    asm("cvt.rna.tf32.f32 %0, %1;" : "=r"(hi) : "f"(x));
    float l = x - __uint_as_float(hi);
    asm("cvt.rna.tf32.f32 %0, %1;" : "=r"(lo) : "f"(l));
}

__device__ __forceinline__ void mma_tf32(float* c, const uint32_t* a, const uint32_t* b) {
    asm("mma.sync.aligned.m16n8k8.row.col.f32.tf32.tf32.f32 "
        "{%0,%1,%2,%3}, {%4,%5,%6,%7}, {%8,%9}, {%0,%1,%2,%3};"
        : "+f"(c[0]), "+f"(c[1]), "+f"(c[2]), "+f"(c[3])
        : "r"(a[0]), "r"(a[1]), "r"(a[2]), "r"(a[3]), "r"(b[0]), "r"(b[1]));
}

#define LDSS 36   // smem row stride (floats) for 32-wide k tiles (+4 pad)

// Load a ROWS x 32 tile (row-major, leading dim ld) into smem [row][k] w/ stride LDSS
template<int ROWS>
__device__ __forceinline__ void load_tile(float* S, const float* src, int ld) {
    int t = threadIdx.x;
    int r = t >> 3, c4 = (t & 7) * 4;
    #pragma unroll
    for (int i = 0; i < ROWS / 32; i++) {
        float4 v = *(const float4*)&src[(size_t)(r + i * 32) * ld + c4];
        *(float4*)&S[(r + i * 32) * LDSS + c4] = v;
    }
}

// One 32-deep k-chunk of 3xTF32 MMAs.
// A smem: [m][k] stride LDSS. B smem: if BK==0: [n][k] stride LDSS; if BK==1: [k][n] stride 68.
template<int MT, int NT, int BK>
__device__ __forceinline__ void mma_chunk(const float* As, const float* Bs,
                                          int mbase, int nbase, float acc[][4]) {
    int lane = threadIdx.x & 31;
    int g = lane >> 2, t4 = lane & 3;
    #pragma unroll
    for (int k8 = 0; k8 < 4; k8++) {
        const int k0 = k8 * 8;
        uint32_t bhi[NT][2], blo[NT][2];
        #pragma unroll
        for (int nt = 0; nt < NT; nt++) {
            float b0, b1;
            if (BK == 0) {
                const float* bp = Bs + (nbase + nt * 8 + g) * LDSS + k0 + t4;
                b0 = bp[0]; b1 = bp[4];
            } else {
                const float* bp = Bs + (k0 + t4) * 68 + nbase + nt * 8 + g;
                b0 = bp[0]; b1 = bp[4 * 68];
            }
            split_tf32(b0, bhi[nt][0], blo[nt][0]);
            split_tf32(b1, bhi[nt][1], blo[nt][1]);
        }
        #pragma unroll
        for (int mt = 0; mt < MT; mt++) {
            const float* ap = As + (mbase + mt * 16 + g) * LDSS + k0 + t4;
            uint32_t ahi[4], alo[4];
            split_tf32(ap[0],             ahi[0], alo[0]);
            split_tf32(ap[8 * LDSS],      ahi[1], alo[1]);
            split_tf32(ap[4],             ahi[2], alo[2]);
            split_tf32(ap[8 * LDSS + 4],  ahi[3], alo[3]);
            #pragma unroll
            for (int nt = 0; nt < NT; nt++) {
                float* c = acc[mt * NT + nt];
                mma_tf32(c, ahi, bhi[nt]);
                mma_tf32(c, ahi, blo[nt]);
                mma_tf32(c, alo, bhi[nt]);
            }
        }
    }
}

// =============================================================================
// QKV projections (tensor): C = X @ W^T, scatter to (B,H,T,DK). 128x128 tiles.
// =============================================================================
__global__ void __launch_bounds__(256) tgemm_qkv(const float* __restrict__ q,
                                                 const float* __restrict__ k,
                                                 const float* __restrict__ v,
                                                 const float* __restrict__ w_q,
                                                 const float* __restrict__ w_k,
                                                 const float* __restrict__ w_v) {
    __shared__ float As[128 * LDSS];
    __shared__ float Bs[128 * LDSS];

    int z = blockIdx.z;
    const float* A = (z == 0) ? q : (z == 1) ? k : v;
    const float* W = (z == 0) ? w_q : (z == 1) ? w_k : w_v;
    float* C = (z == 0) ? g_Q : (z == 1) ? g_K : g_V;

    int m0 = blockIdx.y * 128, n0 = blockIdx.x * 128;
    int wid = threadIdx.x >> 5;
    int mbase = (wid >> 2) * 64, nbase = (wid & 3) * 32;

    float acc[16][4];
    #pragma unroll
    for (int i = 0; i < 16; i++)
        #pragma unroll
        for (int j = 0; j < 4; j++) acc[i][j] = 0.f;

    for (int k0 = 0; k0 < 512; k0 += 32) {
        load_tile<128>(As, A + (size_t)m0 * 512 + k0, 512);
        load_tile<128>(Bs, W + (size_t)n0 * 512 + k0, 512);
        __syncthreads();
        mma_chunk<4, 4, 0>(As, Bs, mbase, nbase, acc);
        __syncthreads();
    }

    int lane = threadIdx.x & 31, g = lane >> 2, t4 = lane & 3;
    #pragma unroll
    for (int mt = 0; mt < 4; mt++) {
        #pragma unroll
        for (int nt = 0; nt < 4; nt++) {
            int col = n0 + nbase + nt * 8 + t4 * 2;
            int h = col >> 6, d = col & 63;
            int r0 = m0 + mbase + mt * 16 + g;
            int r1 = r0 + 8;
            float* c = acc[mt * 4 + nt];
            *(float2*)&C[(size_t)(((r0 >> 10) * NH + h) * T + (r0 & 1023)) * DK + d] =
                make_float2(c[0], c[1]);
            *(float2*)&C[(size_t)(((r1 >> 10) * NH + h) * T + (r1 & 1023)) * DK + d] =
                make_float2(c[2], c[3]);
        }
    }
}

// =============================================================================
// Output projection (tensor): out = g_Ctx @ w_o^T
// =============================================================================
__global__ void __launch_bounds__(256) tgemm_wo(const float* __restrict__ W,
                                                float* __restrict__ out) {
    __shared__ float As[128 * LDSS];
    __shared__ float Bs[128 * LDSS];

    int m0 = blockIdx.y * 128, n0 = blockIdx.x * 128;
    int wid = threadIdx.x >> 5;
    int mbase = (wid >> 2) * 64, nbase = (wid & 3) * 32;

    float acc[16][4];
    #pragma unroll
    for (int i = 0; i < 16; i++)
        #pragma unroll
        for (int j = 0; j < 4; j++) acc[i][j] = 0.f;

    for (int k0 = 0; k0 < 512; k0 += 32) {
        load_tile<128>(As, g_Ctx + (size_t)m0 * 512 + k0, 512);
        load_tile<128>(Bs, W + (size_t)n0 * 512 + k0, 512);
        __syncthreads();
        mma_chunk<4, 4, 0>(As, Bs, mbase, nbase, acc);
        __syncthreads();
    }

    int lane = threadIdx.x & 31, g = lane >> 2, t4 = lane & 3;
    #pragma unroll
    for (int mt = 0; mt < 4; mt++) {
        #pragma unroll
        for (int nt = 0; nt < 4; nt++) {
            int col = n0 + nbase + nt * 8 + t4 * 2;
            int r0 = m0 + mbase + mt * 16 + g;
            int r1 = r0 + 8;
            float* c = acc[mt * 4 + nt];
            *(float2*)&out[(size_t)r0 * 512 + col] = make_float2(c[0], c[1]);
            *(float2*)&out[(size_t)r1 * 512 + col] = make_float2(c[2], c[3]);
        }
    }
}

// =============================================================================
// M = Q K^T per (b,h) (tensor). 128x128 tiles, K=64.
// =============================================================================
__global__ void __launch_bounds__(256) tqk_kernel() {
    __shared__ float As[128 * LDSS];
    __shared__ float Bs[128 * LDSS];

    int bh = blockIdx.z;
    const float* Qb = g_Q + (size_t)bh * T * DK;
    const float* Kb = g_K + (size_t)bh * T * DK;
    int m0 = blockIdx.y * 128, n0 = blockIdx.x * 128;
    int wid = threadIdx.x >> 5;
    int mbase = (wid >> 2) * 64, nbase = (wid & 3) * 32;

    float acc[16][4];
    #pragma unroll
    for (int i = 0; i < 16; i++)
        #pragma unroll
        for (int j = 0; j < 4; j++) acc[i][j] = 0.f;

    for (int k0 = 0; k0 < 64; k0 += 32) {
        load_tile<128>(As, Qb + (size_t)m0 * DK + k0, DK);
        load_tile<128>(Bs, Kb + (size_t)n0 * DK + k0, DK);
        __syncthreads();
        mma_chunk<4, 4, 0>(As, Bs, mbase, nbase, acc);
        __syncthreads();
    }

    float* Mb = g_M + (size_t)bh * T * T;
    int lane = threadIdx.x & 31, g = lane >> 2, t4 = lane & 3;
    #pragma unroll
    for (int mt = 0; mt < 4; mt++) {
        #pragma unroll
        for (int nt = 0; nt < 4; nt++) {
            int col = n0 + nbase + nt * 8 + t4 * 2;
            int r0 = m0 + mbase + mt * 16 + g;
            int r1 = r0 + 8;
            float* c = acc[mt * 4 + nt];
            *(float2*)&Mb[(size_t)r0 * T + col] = make_float2(c[0], c[1]);
            *(float2*)&Mb[(size_t)r1 * T + col] = make_float2(c[2], c[3]);
        }
    }
}

// =============================================================================
// Ctx = A @ V per (b,h) (tensor). 128x64 tiles, K=1024. V kept k-major in smem.
// =============================================================================
__global__ void __launch_bounds__(256) tav_kernel(const float* __restrict__ A) {
    __shared__ float As[128 * LDSS];
    __shared__ float Vs[32 * 68];

    int bh = blockIdx.y;
    int b = bh >> 3, h = bh & 7;
    const float* Ab = A + (size_t)bh * T * T;
    const float* Vb = g_V + (size_t)bh * T * DK;
    int m0 = blockIdx.x * 128;
    int wid = threadIdx.x >> 5;
    int mbase = (wid >> 1) * 32, nbase = (wid & 1) * 32;

    float acc[8][4];
    #pragma unroll
    for (int i = 0; i < 8; i++)
        #pragma unroll
        for (int j = 0; j < 4; j++) acc[i][j] = 0.f;

    int t = threadIdx.x;
    int vr = t >> 4, vc4 = (t & 15) * 4;

    for (int k0 = 0; k0 < T; k0 += 32) {
        load_tile<128>(As, Ab + (size_t)m0 * T + k0, T);
        #pragma unroll
        for (int i = 0; i < 2; i++) {
            float4 vv = *(const float4*)&Vb[(size_t)(k0 + vr + i * 16) * DK + vc4];
            *(float4*)&Vs[(vr + i * 16) * 68 + vc4] = vv;
        }
        __syncthreads();
        mma_chunk<2, 4, 1>(As, Vs, mbase, nbase, acc);
        __syncthreads();
    }

    int lane = threadIdx.x & 31, g = lane >> 2, t4 = lane & 3;
    #pragma unroll
    for (int mt = 0; mt < 2; mt++) {
        #pragma unroll
        for (int nt = 0; nt < 4; nt++) {
            int d = nbase + nt * 8 + t4 * 2;
            int r0 = m0 + mbase + mt * 16 + g;
            int r1 = r0 + 8;
            float* c = acc[mt * 4 + nt];
            *(float2*)&g_Ctx[(size_t)(b * T + r0) * DM + h * DK + d] = make_float2(c[0], c[1]);
            *(float2*)&g_Ctx[(size_t)(b * T + r1) * DM + h * DK + d] = make_float2(c[2], c[3]);
        }
    }
}

// =============================================================================
// Mt = conv3x3(prev, tw) + tb  (8 -> 8 ch). Scalar round-2 kernel, 4 CTAs/SM.
// (Runs fully hidden on the side stream — keep the proven version.)
// =============================================================================
__global__ void __launch_bounds__(256, 4) conv_mt(const float* __restrict__ prev,
                                                  const float* __restrict__ tw,
                                                  const float* __restrict__ tb) {
    __shared__ float s[8][18][66];
    __shared__ float swt[8][9][8];   // [c][t9][o]
    __shared__ float sb[8];

    int b = blockIdx.z;
    int x0 = blockIdx.x * 64;
    int y0 = blockIdx.y * 16;
    int tid = threadIdx.x;
    int tx = tid & 15, ty = tid >> 4;

    for (int e = tid; e < 576; e += 256) {
        int o = e / 72, c = (e % 72) / 9, t9 = e % 9;
        swt[c][t9][o] = tw[e];
    }
    if (tid < 8) sb[tid] = tb[tid];

    for (int e = tid; e < 8 * 18 * 66; e += 256) {
        int c = e / 1188, r = (e % 1188) / 66, cc = e % 66;
        int y = y0 - 1 + r, x = x0 - 1 + cc;
        float val = 0.f;
        if (y >= 0 && y < T && x >= 0 && x < T)
            val = prev[((size_t)(b * 8 + c) * T + y) * T + x];
        s[c][r][cc] = val;
    }
    __syncthreads();

    float2 acc[4][4];
    #pragma unroll
    for (int p = 0; p < 4; p++)
        #pragma unroll
        for (int o2 = 0; o2 < 4; o2++)
            acc[p][o2] = make_float2(sb[o2 * 2], sb[o2 * 2 + 1]);

    int cx = tx * 4;
    #pragma unroll
    for (int c = 0; c < 8; c++) {
        float v[3][6];
        #pragma unroll
        for (int dy = 0; dy < 3; dy++)
            #pragma unroll
            for (int j = 0; j < 6; j++)
                v[dy][j] = s[c][ty + dy][cx + j];
        #pragma unroll
        for (int dy = 0; dy < 3; dy++) {
            #pragma unroll
            for (int dx = 0; dx < 3; dx++) {
                int t9 = dy * 3 + dx;
                float2 w0 = *(float2*)&swt[c][t9][0];
                float2 w1 = *(float2*)&swt[c][t9][2];
                float2 w2 = *(float2*)&swt[c][t9][4];
                float2 w3 = *(float2*)&swt[c][t9][6];
                #pragma unroll
                for (int p = 0; p < 4; p++) {
                    float vv = v[dy][dx + p];
                    float2 vd = make_float2(vv, vv);
                    ffma2(acc[p][0], vd, w0);
                    ffma2(acc[p][1], vd, w1);
                    ffma2(acc[p][2], vd, w2);
                    ffma2(acc[p][3], vd, w3);
                }
            }
        }
    }

    int y = y0 + ty;
    #pragma unroll
    for (int o = 0; o < 8; o++) {
        int o2 = o >> 1;
        float4 ov;
        if (o & 1) ov = make_float4(acc[0][o2].y, acc[1][o2].y, acc[2][o2].y, acc[3][o2].y);
        else       ov = make_float4(acc[0][o2].x, acc[1][o2].x, acc[2][o2].x, acc[3][o2].x);
        *(float4*)&g_Mt[((size_t)(b * 8 + o) * T + y) * T + x0 + cx] = ov;
    }
}

// =============================================================================
// conv_ma as implicit GEMM, v2: PRE-SPLIT tf32 hi/lo in smem + tap-outer order.
// CTA: 64x8 output pixels, 256 threads. smem planes s_hi/s_lo with channel
// stride CXS=12 (conflict-free A-fragment LDS). Warp w = output row y0+w.
// =============================================================================
#define CXS 12          // channel-slot stride (floats)
#define CRS (66 * CXS)  // row stride = 792 floats

// Load + split one 8-channel halo tile (warp w loads channel w).
__device__ __forceinline__ void conv_load_tile_split(float* __restrict__ sh,
                                                     float* __restrict__ sl,
                                                     const float* __restrict__ src_b,
                                                     int y0, int x0) {
    int w = threadIdx.x >> 5, lane = threadIdx.x & 31;
    const float* plane = src_b + (size_t)w * T * T;
    #pragma unroll
    for (int yy = 0; yy < 10; yy++) {
        int y = y0 - 1 + yy;
        bool yok = ((unsigned)y < T);
        int xA = x0 - 1 + lane;
        float v0 = 0.f, v1 = 0.f;
        if (yok) {
            if (xA >= 0) v0 = plane[(size_t)y * T + xA];
            v1 = plane[(size_t)y * T + xA + 32];          // <= 1022, in-bounds
        }
        uint32_t h0, l0, h1, l1;
        split_tf32(v0, h0, l0);
        split_tf32(v1, h1, l1);
        int i0 = yy * CRS + lane * CXS + w;
        int i1 = yy * CRS + (lane + 32) * CXS + w;
        sh[i0] = __uint_as_float(h0); sl[i0] = __uint_as_float(l0);
        sh[i1] = __uint_as_float(h1); sl[i1] = __uint_as_float(l1);
        if (lane < 2) {
            int xC = x0 + 63 + lane;
            float v2 = 0.f;
            if (yok && xC < T) v2 = plane[(size_t)y * T + xC];
            uint32_t h2, l2;
            split_tf32(v2, h2, l2);
            int i2 = yy * CRS + (64 + lane) * CXS + w;
            sh[i2] = __uint_as_float(h2); sl[i2] = __uint_as_float(l2);
        }
    }
}

// Weights for one 8-channel pass: thread (g,t4) supplies B[n=g][k=t4,(t4+4)].
__device__ __forceinline__ void conv_load_wregs(const float* __restrict__ W, int cin, int c0,
                                                int g, int t4,
                                                uint32_t bh[9][2], uint32_t bl[9][2]) {
    #pragma unroll
    for (int tap = 0; tap < 9; tap++) {
        float w0 = W[(g * cin + c0 + t4) * 9 + tap];
        float w1 = W[(g * cin + c0 + t4 + 4) * 9 + tap];
        split_tf32(w0, bh[tap][0], bl[tap][0]);
        split_tf32(w1, bh[tap][1], bl[tap][1]);
    }
}

// One 8-channel pass. Tap OUTER, m-tile INNER -> 4 independent MMA chains.
__device__ __forceinline__ void conv_mma_pass2(const float* __restrict__ sh,
                                               const float* __restrict__ sl, int g,
                                               const uint32_t bh[9][2],
                                               const uint32_t bl[9][2],
                                               float acc[4][4]) {
    #pragma unroll
    for (int dy = 0; dy < 3; dy++) {
        #pragma unroll
        for (int dx = 0; dx < 3; dx++) {
            const int tap = dy * 3 + dx;
            const int off = dy * CRS + dx * CXS + g * CXS;
            #pragma unroll
            for (int xt = 0; xt < 4; xt++) {
                const float* ph = sh + off + xt * 16 * CXS;
                const float* pl = sl + off + xt * 16 * CXS;
                uint32_t ahi[4], alo[4];
                ahi[0] = __float_as_uint(ph[0]);
                ahi[1] = __float_as_uint(ph[8 * CXS]);
                ahi[2] = __float_as_uint(ph[4]);
                ahi[3] = __float_as_uint(ph[8 * CXS + 4]);
                alo[0] = __float_as_uint(pl[0]);
                alo[1] = __float_as_uint(pl[8 * CXS]);
                alo[2] = __float_as_uint(pl[4]);
                alo[3] = __float_as_uint(pl[8 * CXS + 4]);
                mma_tf32(acc[xt], ahi, bh[tap]);
                mma_tf32(acc[xt], ahi, bl[tap]);
                mma_tf32(acc[xt], alo, bh[tap]);
            }
        }
    }
}

// Apre = (conv3x3(concat(M, Mt), aw) + ab) / 8, masked -> A region of d_out.
__global__ void __launch_bounds__(256) conv_ma_mma2(const float* __restrict__ aw,
                                                    const float* __restrict__ ab,
                                                    const int* __restrict__ mask,
                                                    float* __restrict__ Apre) {
    __shared__ float s_hi[10 * CRS];
    __shared__ float s_lo[10 * CRS];
    int b = blockIdx.z, x0 = blockIdx.x * 64, y0 = blockIdx.y * 8;
    int w = threadIdx.x >> 5, lane = threadIdx.x & 31;
    int g = lane >> 2, t4 = lane & 3;

    float acc[4][4];
    #pragma unroll
    for (int i = 0; i < 4; i++)
        #pragma unroll
        for (int j = 0; j < 4; j++) acc[i][j] = 0.f;

    #pragma unroll
    for (int pass = 0; pass < 2; pass++) {
        const float* src = pass ? g_Mt : g_M;
        if (pass) __syncthreads();   // previous pass compute done before overwrite
        conv_load_tile_split(s_hi, s_lo, src + (size_t)b * 8 * T * T, y0, x0);

        uint32_t bh[9][2], bl[9][2];
        conv_load_wregs(aw, 16, pass * 8, g, t4, bh, bl);
        __syncthreads();

        conv_mma_pass2(s_hi + w * CRS + t4, s_lo + w * CRS + t4, g, bh, bl, acc);
    }

    float bias0 = ab[2 * t4], bias1 = ab[2 * t4 + 1];
    int y = y0 + w;
    float* p0 = &Apre[((size_t)(b * 8 + 2 * t4) * T + y) * T];
    float* p1 = &Apre[((size_t)(b * 8 + 2 * t4 + 1) * T + y) * T];
    #pragma unroll
    for (int xt = 0; xt < 4; xt++) {
        int px = x0 + xt * 16 + g;
        int mk0 = mask[b * T + px];
        int mk1 = mask[b * T + px + 8];
        float r00 = (acc[xt][0] + bias0) * 0.125f;
        float r01 = (acc[xt][1] + bias1) * 0.125f;
        float r10 = (acc[xt][2] + bias0) * 0.125f;
        float r11 = (acc[xt][3] + bias1) * 0.125f;
        if (mk0 == 0) { r00 = -1e9f; r01 = -1e9f; }
        if (mk1 == 0) { r10 = -1e9f; r11 = -1e9f; }
        p0[px]     = r00;
        p1[px]     = r01;
        p0[px + 8] = r10;
        p1[px + 8] = r11;
    }
}

// ---------------- warp-per-row softmax (rows of 1024), in place ---------------
__global__ void __launch_bounds__(256) softmax_kernel(float* __restrict__ A) {
    int row = blockIdx.x * 8 + (threadIdx.x >> 5);
    int lane = threadIdx.x & 31;
    float* p = A + (size_t)row * 1024;

    float4 v[8];
    #pragma unroll
    for (int j = 0; j < 8; j++) v[j] = *(float4*)&p[(j * 32 + lane) * 4];

    float mx = -3.4e38f;
    #pragma unroll
    for (int j = 0; j < 8; j++)
        mx = fmaxf(mx, fmaxf(fmaxf(v[j].x, v[j].y), fmaxf(v[j].z, v[j].w)));
    #pragma unroll
    for (int o = 16; o > 0; o >>= 1) mx = fmaxf(mx, __shfl_xor_sync(~0u, mx, o));

    float s = 0.f;
    #pragma unroll
    for (int j = 0; j < 8; j++) {
        v[j].x = __expf(v[j].x - mx); v[j].y = __expf(v[j].y - mx);
        v[j].z = __expf(v[j].z - mx); v[j].w = __expf(v[j].w - mx);
        s += v[j].x + v[j].y + v[j].z + v[j].w;
    }
    #pragma unroll
    for (int o = 16; o > 0; o >>= 1) s += __shfl_xor_sync(~0u, s, o);
    float inv = 1.f / s;

    #pragma unroll
    for (int j = 0; j < 8; j++) {
        v[j].x *= inv; v[j].y *= inv; v[j].z *= inv; v[j].w *= inv;
        *(float4*)&p[(j * 32 + lane) * 4] = v[j];
    }
}

// ---------------- launcher ---------------------------------------------------
extern "C" void kernel_launch(void* const* d_in, const int* in_sizes, int n_in,
                              void* d_out, int out_size) {
    const float* q    = (const float*)d_in[0];
    const float* k    = (const float*)d_in[1];
    const float* v    = (const float*)d_in[2];
    const int*   mask = (const int*)  d_in[3];
    const float* prev = (const float*)d_in[4];
    const float* w_q  = (const float*)d_in[5];
    const float* w_k  = (const float*)d_in[6];
    const float* w_v  = (const float*)d_in[7];
    const float* w_o  = (const float*)d_in[8];
    const float* tw   = (const float*)d_in[9];
    const float* tb   = (const float*)d_in[10];
    const float* aw   = (const float*)d_in[11];
    const float* ab   = (const float*)d_in[12];

    float* out  = (float*)d_out;
    float* Aout = out + (size_t)B * T * DM;

    static cudaStream_t s_side = ([]() {
        cudaStream_t s; cudaStreamCreateWithFlags(&s, cudaStreamNonBlocking); return s;
    })();
    static cudaEvent_t ev_fork = ([]() {
        cudaEvent_t e; cudaEventCreateWithFlags(&e, cudaEventDisableTiming); return e;
    })();
    static cudaEvent_t ev_join = ([]() {
        cudaEvent_t e; cudaEventCreateWithFlags(&e, cudaEventDisableTiming); return e;
    })();

    // ---- fork: conv_mt (depends only on prev) runs on side stream ----------
    cudaEventRecord(ev_fork, 0);
    cudaStreamWaitEvent(s_side, ev_fork, 0);
    conv_mt<<<dim3(T / 64, T / 16, B), 256, 0, s_side>>>(prev, tw, tb);
    cudaEventRecord(ev_join, s_side);

    // ---- main chain on default stream (overlaps with conv_mt) --------------
    tgemm_qkv<<<dim3(DM / 128, (B * T) / 128, 3), 256>>>(q, k, v, w_q, w_k, w_v);
    tqk_kernel<<<dim3(T / 128, T / 128, B * NH), 256>>>();

    // ---- join: conv_ma needs both g_M and g_Mt -----------------------------
    cudaStreamWaitEvent(0, ev_join, 0);
    conv_ma_mma2<<<dim3(T / 64, T / 8, B), 256>>>(aw, ab, mask, Aout);

    softmax_kernel<<<(B * NH * T) / 8, 256>>>(Aout);
    tav_kernel<<<dim3(T / 128, B * NH), 256>>>(Aout);
    tgemm_wo<<<dim3(DM / 128, (B * T) / 128), 256>>>(w_o, out);
}

// round 15
// speedup vs baseline: 1.3599x; 1.1082x over previous
#include <cuda_runtime.h>
#include <cstdint>

#define B  4
#define T  1024
#define DM 512
#define NH 8
#define DK 64

// ---------------- scratch (device globals; no allocs allowed) ----------------
__device__ float g_Q[B * NH * T * DK];
__device__ float g_K[B * NH * T * DK];
__device__ float g_V[B * NH * T * DK];
__device__ float g_M[(size_t)B * NH * T * T];
__device__ float g_Mt[(size_t)B * NH * T * T];
__device__ float g_Ctx[B * T * DM];

// packed f32x2 FMA (PTX-only) — used by the conv kernels
union F2U { float2 f; unsigned long long u; };
__device__ __forceinline__ void ffma2(float2& c, float2 a, float2 b) {
    F2U A, Bv, C;
    A.f = a; Bv.f = b; C.f = c;
    asm("fma.rn.f32x2 %0, %1, %2, %0;" : "+l"(C.u) : "l"(A.u), "l"(Bv.u));
    c = C.f;
}

// =============================================================================
// Tensor-core building blocks: split-TF32 (3xTF32) m16n8k8 MMA
// =============================================================================
__device__ __forceinline__ void split_tf32(float x, uint32_t& hi, uint32_t& lo) {
    asm("cvt.rna.tf32.f32 %0, %1;" : "=r"(hi) : "f"(x));
    float l = x - __uint_as_float(hi);
    asm("cvt.rna.tf32.f32 %0, %1;" : "=r"(lo) : "f"(l));
}

__device__ __forceinline__ void mma_tf32(float* c, const uint32_t* a, const uint32_t* b) {
    asm("mma.sync.aligned.m16n8k8.row.col.f32.tf32.tf32.f32 "
        "{%0,%1,%2,%3}, {%4,%5,%6,%7}, {%8,%9}, {%0,%1,%2,%3};"
        : "+f"(c[0]), "+f"(c[1]), "+f"(c[2]), "+f"(c[3])
        : "r"(a[0]), "r"(a[1]), "r"(a[2]), "r"(a[3]), "r"(b[0]), "r"(b[1]));
}

#define LDSS 36   // smem row stride (floats) for 32-wide k tiles (+4 pad)

// Load a ROWS x 32 tile (row-major, leading dim ld) into smem [row][k] w/ stride LDSS
template<int ROWS>
__device__ __forceinline__ void load_tile(float* S, const float* src, int ld) {
    int t = threadIdx.x;
    int r = t >> 3, c4 = (t & 7) * 4;
    #pragma unroll
    for (int i = 0; i < ROWS / 32; i++) {
        float4 v = *(const float4*)&src[(size_t)(r + i * 32) * ld + c4];
        *(float4*)&S[(r + i * 32) * LDSS + c4] = v;
    }
}

// One 32-deep k-chunk of 3xTF32 MMAs.
// A smem: [m][k] stride LDSS. B smem: if BK==0: [n][k] stride LDSS; if BK==1: [k][n] stride 68.
template<int MT, int NT, int BK>
__device__ __forceinline__ void mma_chunk(const float* As, const float* Bs,
                                          int mbase, int nbase, float acc[][4]) {
    int lane = threadIdx.x & 31;
    int g = lane >> 2, t4 = lane & 3;
    #pragma unroll
    for (int k8 = 0; k8 < 4; k8++) {
        const int k0 = k8 * 8;
        uint32_t bhi[NT][2], blo[NT][2];
        #pragma unroll
        for (int nt = 0; nt < NT; nt++) {
            float b0, b1;
            if (BK == 0) {
                const float* bp = Bs + (nbase + nt * 8 + g) * LDSS + k0 + t4;
                b0 = bp[0]; b1 = bp[4];
            } else {
                const float* bp = Bs + (k0 + t4) * 68 + nbase + nt * 8 + g;
                b0 = bp[0]; b1 = bp[4 * 68];
            }
            split_tf32(b0, bhi[nt][0], blo[nt][0]);
            split_tf32(b1, bhi[nt][1], blo[nt][1]);
        }
        #pragma unroll
        for (int mt = 0; mt < MT; mt++) {
            const float* ap = As + (mbase + mt * 16 + g) * LDSS + k0 + t4;
            uint32_t ahi[4], alo[4];
            split_tf32(ap[0],             ahi[0], alo[0]);
            split_tf32(ap[8 * LDSS],      ahi[1], alo[1]);
            split_tf32(ap[4],             ahi[2], alo[2]);
            split_tf32(ap[8 * LDSS + 4],  ahi[3], alo[3]);
            #pragma unroll
            for (int nt = 0; nt < NT; nt++) {
                float* c = acc[mt * NT + nt];
                mma_tf32(c, ahi, bhi[nt]);
                mma_tf32(c, ahi, blo[nt]);
                mma_tf32(c, alo, bhi[nt]);
            }
        }
    }
}

// =============================================================================
// QKV projections (tensor): C = X @ W^T, scatter to (B,H,T,DK). 128x128 tiles.
// =============================================================================
__global__ void __launch_bounds__(256) tgemm_qkv(const float* __restrict__ q,
                                                 const float* __restrict__ k,
                                                 const float* __restrict__ v,
                                                 const float* __restrict__ w_q,
                                                 const float* __restrict__ w_k,
                                                 const float* __restrict__ w_v) {
    __shared__ float As[128 * LDSS];
    __shared__ float Bs[128 * LDSS];

    int z = blockIdx.z;
    const float* A = (z == 0) ? q : (z == 1) ? k : v;
    const float* W = (z == 0) ? w_q : (z == 1) ? w_k : w_v;
    float* C = (z == 0) ? g_Q : (z == 1) ? g_K : g_V;

    int m0 = blockIdx.y * 128, n0 = blockIdx.x * 128;
    int wid = threadIdx.x >> 5;
    int mbase = (wid >> 2) * 64, nbase = (wid & 3) * 32;

    float acc[16][4];
    #pragma unroll
    for (int i = 0; i < 16; i++)
        #pragma unroll
        for (int j = 0; j < 4; j++) acc[i][j] = 0.f;

    for (int k0 = 0; k0 < 512; k0 += 32) {
        load_tile<128>(As, A + (size_t)m0 * 512 + k0, 512);
        load_tile<128>(Bs, W + (size_t)n0 * 512 + k0, 512);
        __syncthreads();
        mma_chunk<4, 4, 0>(As, Bs, mbase, nbase, acc);
        __syncthreads();
    }

    int lane = threadIdx.x & 31, g = lane >> 2, t4 = lane & 3;
    #pragma unroll
    for (int mt = 0; mt < 4; mt++) {
        #pragma unroll
        for (int nt = 0; nt < 4; nt++) {
            int col = n0 + nbase + nt * 8 + t4 * 2;
            int h = col >> 6, d = col & 63;
            int r0 = m0 + mbase + mt * 16 + g;
            int r1 = r0 + 8;
            float* c = acc[mt * 4 + nt];
            *(float2*)&C[(size_t)(((r0 >> 10) * NH + h) * T + (r0 & 1023)) * DK + d] =
                make_float2(c[0], c[1]);
            *(float2*)&C[(size_t)(((r1 >> 10) * NH + h) * T + (r1 & 1023)) * DK + d] =
                make_float2(c[2], c[3]);
        }
    }
}

// =============================================================================
// Output projection (tensor): out = g_Ctx @ w_o^T
// =============================================================================
__global__ void __launch_bounds__(256) tgemm_wo(const float* __restrict__ W,
                                                float* __restrict__ out) {
    __shared__ float As[128 * LDSS];
    __shared__ float Bs[128 * LDSS];

    int m0 = blockIdx.y * 128, n0 = blockIdx.x * 128;
    int wid = threadIdx.x >> 5;
    int mbase = (wid >> 2) * 64, nbase = (wid & 3) * 32;

    float acc[16][4];
    #pragma unroll
    for (int i = 0; i < 16; i++)
        #pragma unroll
        for (int j = 0; j < 4; j++) acc[i][j] = 0.f;

    for (int k0 = 0; k0 < 512; k0 += 32) {
        load_tile<128>(As, g_Ctx + (size_t)m0 * 512 + k0, 512);
        load_tile<128>(Bs, W + (size_t)n0 * 512 + k0, 512);
        __syncthreads();
        mma_chunk<4, 4, 0>(As, Bs, mbase, nbase, acc);
        __syncthreads();
    }

    int lane = threadIdx.x & 31, g = lane >> 2, t4 = lane & 3;
    #pragma unroll
    for (int mt = 0; mt < 4; mt++) {
        #pragma unroll
        for (int nt = 0; nt < 4; nt++) {
            int col = n0 + nbase + nt * 8 + t4 * 2;
            int r0 = m0 + mbase + mt * 16 + g;
            int r1 = r0 + 8;
            float* c = acc[mt * 4 + nt];
            *(float2*)&out[(size_t)r0 * 512 + col] = make_float2(c[0], c[1]);
            *(float2*)&out[(size_t)r1 * 512 + col] = make_float2(c[2], c[3]);
        }
    }
}

// =============================================================================
// M = Q K^T per (b,h) (tensor). 128x128 tiles, K=64.
// =============================================================================
__global__ void __launch_bounds__(256) tqk_kernel() {
    __shared__ float As[128 * LDSS];
    __shared__ float Bs[128 * LDSS];

    int bh = blockIdx.z;
    const float* Qb = g_Q + (size_t)bh * T * DK;
    const float* Kb = g_K + (size_t)bh * T * DK;
    int m0 = blockIdx.y * 128, n0 = blockIdx.x * 128;
    int wid = threadIdx.x >> 5;
    int mbase = (wid >> 2) * 64, nbase = (wid & 3) * 32;

    float acc[16][4];
    #pragma unroll
    for (int i = 0; i < 16; i++)
        #pragma unroll
        for (int j = 0; j < 4; j++) acc[i][j] = 0.f;

    for (int k0 = 0; k0 < 64; k0 += 32) {
        load_tile<128>(As, Qb + (size_t)m0 * DK + k0, DK);
        load_tile<128>(Bs, Kb + (size_t)n0 * DK + k0, DK);
        __syncthreads();
        mma_chunk<4, 4, 0>(As, Bs, mbase, nbase, acc);
        __syncthreads();
    }

    float* Mb = g_M + (size_t)bh * T * T;
    int lane = threadIdx.x & 31, g = lane >> 2, t4 = lane & 3;
    #pragma unroll
    for (int mt = 0; mt < 4; mt++) {
        #pragma unroll
        for (int nt = 0; nt < 4; nt++) {
            int col = n0 + nbase + nt * 8 + t4 * 2;
            int r0 = m0 + mbase + mt * 16 + g;
            int r1 = r0 + 8;
            float* c = acc[mt * 4 + nt];
            *(float2*)&Mb[(size_t)r0 * T + col] = make_float2(c[0], c[1]);
            *(float2*)&Mb[(size_t)r1 * T + col] = make_float2(c[2], c[3]);
        }
    }
}

// =============================================================================
// FUSED softmax + Ctx = A @ V per (b,h) (tensor). 128x64 tiles, K=1024.
// Prologue: each CTA owns rows [m0, m0+128) of slice bh exclusively; computes
// per-row max + exp-sum. GEMM loop: A tiles get exp(x-mx)*inv applied on load
// into smem AND the normalized value is written back to the A output region.
// =============================================================================
__global__ void __launch_bounds__(256) tav_fused(float* __restrict__ A) {
    __shared__ float As[128 * LDSS];
    __shared__ float Vs[32 * 68];
    __shared__ float s_mx[128];
    __shared__ float s_inv[128];

    int bh = blockIdx.y;
    int b = bh >> 3, h = bh & 7;
    float* Ab = A + (size_t)bh * T * T;
    const float* Vb = g_V + (size_t)bh * T * DK;
    int m0 = blockIdx.x * 128;
    int wid = threadIdx.x >> 5;
    int lane = threadIdx.x & 31;
    int mbase = (wid >> 1) * 32, nbase = (wid & 1) * 32;

    // ---- prologue: per-row max and exp-sum over the 1024-wide row ----------
    #pragma unroll 1
    for (int i = 0; i < 16; i++) {
        int r = wid * 16 + i;
        const float* rp = Ab + (size_t)(m0 + r) * T;
        float4 vv[8];
        #pragma unroll
        for (int jj = 0; jj < 8; jj++)
            vv[jj] = *(const float4*)&rp[(jj * 32 + lane) * 4];

        float mx = -3.4e38f;
        #pragma unroll
        for (int jj = 0; jj < 8; jj++)
            mx = fmaxf(mx, fmaxf(fmaxf(vv[jj].x, vv[jj].y), fmaxf(vv[jj].z, vv[jj].w)));
        #pragma unroll
        for (int o = 16; o > 0; o >>= 1) mx = fmaxf(mx, __shfl_xor_sync(~0u, mx, o));

        float s = 0.f;
        #pragma unroll
        for (int jj = 0; jj < 8; jj++) {
            s += __expf(vv[jj].x - mx) + __expf(vv[jj].y - mx)
               + __expf(vv[jj].z - mx) + __expf(vv[jj].w - mx);
        }
        #pragma unroll
        for (int o = 16; o > 0; o >>= 1) s += __shfl_xor_sync(~0u, s, o);

        if (lane == 0) { s_mx[r] = mx; s_inv[r] = 1.f / s; }
    }
    __syncthreads();

    // ---- GEMM over K=1024 with exp-normalize-on-load + writeback -----------
    float acc[8][4];
    #pragma unroll
    for (int i = 0; i < 8; i++)
        #pragma unroll
        for (int j = 0; j < 4; j++) acc[i][j] = 0.f;

    int t = threadIdx.x;
    int ar = t >> 3, ac4 = (t & 7) * 4;
    int vr = t >> 4, vc4 = (t & 15) * 4;

    for (int k0 = 0; k0 < T; k0 += 32) {
        // A tile: load raw, normalize, stash in smem, write normalized to gmem
        #pragma unroll
        for (int i = 0; i < 4; i++) {
            int rr = ar + i * 32;
            float* gp = &Ab[(size_t)(m0 + rr) * T + k0 + ac4];
            float4 v = *(const float4*)gp;
            float m = s_mx[rr], is = s_inv[rr];
            v.x = __expf(v.x - m) * is;
            v.y = __expf(v.y - m) * is;
            v.z = __expf(v.z - m) * is;
            v.w = __expf(v.w - m) * is;
            *(float4*)&As[rr * LDSS + ac4] = v;
            *(float4*)gp = v;
        }
        #pragma unroll
        for (int i = 0; i < 2; i++) {
            float4 vv = *(const float4*)&Vb[(size_t)(k0 + vr + i * 16) * DK + vc4];
            *(float4*)&Vs[(vr + i * 16) * 68 + vc4] = vv;
        }
        __syncthreads();
        mma_chunk<2, 4, 1>(As, Vs, mbase, nbase, acc);
        __syncthreads();
    }

    int g = lane >> 2, t4 = lane & 3;
    #pragma unroll
    for (int mt = 0; mt < 2; mt++) {
        #pragma unroll
        for (int nt = 0; nt < 4; nt++) {
            int d = nbase + nt * 8 + t4 * 2;
            int r0 = m0 + mbase + mt * 16 + g;
            int r1 = r0 + 8;
            float* c = acc[mt * 4 + nt];
            *(float2*)&g_Ctx[(size_t)(b * T + r0) * DM + h * DK + d] = make_float2(c[0], c[1]);
            *(float2*)&g_Ctx[(size_t)(b * T + r1) * DM + h * DK + d] = make_float2(c[2], c[3]);
        }
    }
}

// =============================================================================
// Mt = conv3x3(prev, tw) + tb  (8 -> 8 ch). Scalar round-2 kernel, 4 CTAs/SM.
// =============================================================================
__global__ void __launch_bounds__(256, 4) conv_mt(const float* __restrict__ prev,
                                                  const float* __restrict__ tw,
                                                  const float* __restrict__ tb) {
    __shared__ float s[8][18][66];
    __shared__ float swt[8][9][8];   // [c][t9][o]
    __shared__ float sb[8];

    int b = blockIdx.z;
    int x0 = blockIdx.x * 64;
    int y0 = blockIdx.y * 16;
    int tid = threadIdx.x;
    int tx = tid & 15, ty = tid >> 4;

    for (int e = tid; e < 576; e += 256) {
        int o = e / 72, c = (e % 72) / 9, t9 = e % 9;
        swt[c][t9][o] = tw[e];
    }
    if (tid < 8) sb[tid] = tb[tid];

    for (int e = tid; e < 8 * 18 * 66; e += 256) {
        int c = e / 1188, r = (e % 1188) / 66, cc = e % 66;
        int y = y0 - 1 + r, x = x0 - 1 + cc;
        float val = 0.f;
        if (y >= 0 && y < T && x >= 0 && x < T)
            val = prev[((size_t)(b * 8 + c) * T + y) * T + x];
        s[c][r][cc] = val;
    }
    __syncthreads();

    float2 acc[4][4];
    #pragma unroll
    for (int p = 0; p < 4; p++)
        #pragma unroll
        for (int o2 = 0; o2 < 4; o2++)
            acc[p][o2] = make_float2(sb[o2 * 2], sb[o2 * 2 + 1]);

    int cx = tx * 4;
    #pragma unroll
    for (int c = 0; c < 8; c++) {
        float v[3][6];
        #pragma unroll
        for (int dy = 0; dy < 3; dy++)
            #pragma unroll
            for (int j = 0; j < 6; j++)
                v[dy][j] = s[c][ty + dy][cx + j];
        #pragma unroll
        for (int dy = 0; dy < 3; dy++) {
            #pragma unroll
            for (int dx = 0; dx < 3; dx++) {
                int t9 = dy * 3 + dx;
                float2 w0 = *(float2*)&swt[c][t9][0];
                float2 w1 = *(float2*)&swt[c][t9][2];
                float2 w2 = *(float2*)&swt[c][t9][4];
                float2 w3 = *(float2*)&swt[c][t9][6];
                #pragma unroll
                for (int p = 0; p < 4; p++) {
                    float vv = v[dy][dx + p];
                    float2 vd = make_float2(vv, vv);
                    ffma2(acc[p][0], vd, w0);
                    ffma2(acc[p][1], vd, w1);
                    ffma2(acc[p][2], vd, w2);
                    ffma2(acc[p][3], vd, w3);
                }
            }
        }
    }

    int y = y0 + ty;
    #pragma unroll
    for (int o = 0; o < 8; o++) {
        int o2 = o >> 1;
        float4 ov;
        if (o & 1) ov = make_float4(acc[0][o2].y, acc[1][o2].y, acc[2][o2].y, acc[3][o2].y);
        else       ov = make_float4(acc[0][o2].x, acc[1][o2].x, acc[2][o2].x, acc[3][o2].x);
        *(float4*)&g_Mt[((size_t)(b * 8 + o) * T + y) * T + x0 + cx] = ov;
    }
}

// =============================================================================
// Apre = (conv3x3(concat(M, Mt), aw) + ab) / 8, masked. Scalar, 4 CTAs/SM.
// =============================================================================
__global__ void __launch_bounds__(256, 4) conv_ma(const float* __restrict__ aw,
                                                  const float* __restrict__ ab,
                                                  const int* __restrict__ mask,
                                                  float* __restrict__ Apre) {
    __shared__ float s[8][18][66];
    __shared__ float swa[16][9][8];  // [c][t9][o]
    __shared__ float sab[8];

    int b = blockIdx.z;
    int x0 = blockIdx.x * 64;
    int y0 = blockIdx.y * 16;
    int tid = threadIdx.x;
    int tx = tid & 15, ty = tid >> 4;

    for (int e = tid; e < 1152; e += 256) {
        int o = e / 144, c = (e % 144) / 9, t9 = e % 9;
        swa[c][t9][o] = aw[e];
    }
    if (tid < 8) sab[tid] = ab[tid];

    float2 acc[4][4];
    #pragma unroll
    for (int p = 0; p < 4; p++)
        #pragma unroll
        for (int o2 = 0; o2 < 4; o2++)
            acc[p][o2] = make_float2(0.f, 0.f);

    int cx = tx * 4;

    #pragma unroll
    for (int pass = 0; pass < 2; pass++) {
        const float* src = pass ? g_Mt : g_M;
        for (int e = tid; e < 8 * 18 * 66; e += 256) {
            int c = e / 1188, r = (e % 1188) / 66, cc = e % 66;
            int y = y0 - 1 + r, x = x0 - 1 + cc;
            float val = 0.f;
            if (y >= 0 && y < T && x >= 0 && x < T)
                val = src[((size_t)(b * 8 + c) * T + y) * T + x];
            s[c][r][cc] = val;
        }
        __syncthreads();

        #pragma unroll
        for (int c = 0; c < 8; c++) {
            int cw = c + pass * 8;
            float v[3][6];
            #pragma unroll
            for (int dy = 0; dy < 3; dy++)
                #pragma unroll
                for (int j = 0; j < 6; j++)
                    v[dy][j] = s[c][ty + dy][cx + j];
            #pragma unroll
            for (int dy = 0; dy < 3; dy++) {
                #pragma unroll
                for (int dx = 0; dx < 3; dx++) {
                    int t9 = dy * 3 + dx;
                    float2 w0 = *(float2*)&swa[cw][t9][0];
                    float2 w1 = *(float2*)&swa[cw][t9][2];
                    float2 w2 = *(float2*)&swa[cw][t9][4];
                    float2 w3 = *(float2*)&swa[cw][t9][6];
                    #pragma unroll
                    for (int p = 0; p < 4; p++) {
                        float vv = v[dy][dx + p];
                        float2 vd = make_float2(vv, vv);
                        ffma2(acc[p][0], vd, w0);
                        ffma2(acc[p][1], vd, w1);
                        ffma2(acc[p][2], vd, w2);
                        ffma2(acc[p][3], vd, w3);
                    }
                }
            }
        }
        if (pass == 0) __syncthreads();
    }

    int y = y0 + ty;
    int xg = x0 + cx;
    bool mk[4];
    #pragma unroll
    for (int p = 0; p < 4; p++) mk[p] = (mask[b * T + xg + p] == 0);

    #pragma unroll
    for (int o = 0; o < 8; o++) {
        int o2 = o >> 1;
        float r0, r1, r2, r3;
        if (o & 1) { r0 = acc[0][o2].y; r1 = acc[1][o2].y; r2 = acc[2][o2].y; r3 = acc[3][o2].y; }
        else       { r0 = acc[0][o2].x; r1 = acc[1][o2].x; r2 = acc[2][o2].x; r3 = acc[3][o2].x; }
        float bias = sab[o];
        r0 = (r0 + bias) * 0.125f; r1 = (r1 + bias) * 0.125f;
        r2 = (r2 + bias) * 0.125f; r3 = (r3 + bias) * 0.125f;
        if (mk[0]) r0 = -1e9f;
        if (mk[1]) r1 = -1e9f;
        if (mk[2]) r2 = -1e9f;
        if (mk[3]) r3 = -1e9f;
        float4 ov = make_float4(r0, r1, r2, r3);
        *(float4*)&Apre[((size_t)(b * 8 + o) * T + y) * T + xg] = ov;
    }
}

// ---------------- launcher (round-10 topology: 1 side stream, 2 events) -----
extern "C" void kernel_launch(void* const* d_in, const int* in_sizes, int n_in,
                              void* d_out, int out_size) {
    const float* q    = (const float*)d_in[0];
    const float* k    = (const float*)d_in[1];
    const float* v    = (const float*)d_in[2];
    const int*   mask = (const int*)  d_in[3];
    const float* prev = (const float*)d_in[4];
    const float* w_q  = (const float*)d_in[5];
    const float* w_k  = (const float*)d_in[6];
    const float* w_v  = (const float*)d_in[7];
    const float* w_o  = (const float*)d_in[8];
    const float* tw   = (const float*)d_in[9];
    const float* tb   = (const float*)d_in[10];
    const float* aw   = (const float*)d_in[11];
    const float* ab   = (const float*)d_in[12];

    float* out  = (float*)d_out;
    float* Aout = out + (size_t)B * T * DM;

    // One-time host-side resources (created on the correctness call, reused
    // under graph capture; only event record/wait are issued per call).
    static cudaStream_t s_side = ([]() {
        cudaStream_t s; cudaStreamCreateWithFlags(&s, cudaStreamNonBlocking); return s;
    })();
    static cudaEvent_t ev_fork = ([]() {
        cudaEvent_t e; cudaEventCreateWithFlags(&e, cudaEventDisableTiming); return e;
    })();
    static cudaEvent_t ev_join = ([]() {
        cudaEvent_t e; cudaEventCreateWithFlags(&e, cudaEventDisableTiming); return e;
    })();

    // ---- fork: conv_mt (depends only on prev) runs on side stream ----------
    cudaEventRecord(ev_fork, 0);
    cudaStreamWaitEvent(s_side, ev_fork, 0);
    conv_mt<<<dim3(T / 64, T / 16, B), 256, 0, s_side>>>(prev, tw, tb);
    cudaEventRecord(ev_join, s_side);

    // ---- main chain on default stream (overlaps with conv_mt) --------------
    tgemm_qkv<<<dim3(DM / 128, (B * T) / 128, 3), 256>>>(q, k, v, w_q, w_k, w_v);
    tqk_kernel<<<dim3(T / 128, T / 128, B * NH), 256>>>();

    // ---- join: conv_ma needs both g_M and g_Mt -----------------------------
    cudaStreamWaitEvent(0, ev_join, 0);
    conv_ma<<<dim3(T / 64, T / 16, B), 256>>>(aw, ab, mask, Aout);

    // fused softmax + A@V (writes normalized A in place + g_Ctx)
    tav_fused<<<dim3(T / 128, B * NH), 256>>>(Aout);

    // out = Ctx @ w_o^T
    tgemm_wo<<<dim3(DM / 128, (B * T) / 128), 256>>>(w_o, out);
}